// round 13
// baseline (speedup 1.0000x reference)
#include <cuda_runtime.h>
#include <cuda_fp16.h>
#include <math.h>
#include <stdint.h>

// NoisyTopKRouter: B=4, S=4096, D=2048, E=64, K=8
// Exact 3-way bf16 split mma.sync + Kahan (fp16-scaled cmp in smem);
// 256-thread CTAs, 2 CTAs/SM to fill barrier bubbles cross-CTA.
// out: probs [T*E] f32, topk_idx [T*K] f32, new_bias [E] f32

namespace {

constexpr int T_TOK  = 16384;
constexpr int DDIM   = 2048;
constexpr int E      = 64;
constexpr int KSEL   = 8;
constexpr int TILE_T = 64;
constexpr int KC     = 32;               // fp32 k per chunk
constexpr int NCHUNK = DDIM / KC;        // 64
constexpr int NTHR   = 256;
constexpr int ROWB   = 80;               // smem row stride bytes (16B-aligned)
constexpr int A_H = 0;
constexpr int A_M = A_H + TILE_T * ROWB;      // 5120
constexpr int A_L = A_M + TILE_T * ROWB;      // 10240
constexpr int B_H = A_L + TILE_T * ROWB;      // 15360
constexpr int B_M = B_H + 128 * ROWB;         // 25600
constexpr int B_L = B_M + 128 * ROWB;         // 35840
constexpr int STAGE_B = B_L + 128 * ROWB;     // 46080
constexpr int CMP_OFF = 2 * STAGE_B;          // 92160
constexpr int SMEM_BYTES = CMP_OFF + 32 * NTHR * 2;   // 108544 (2 CTAs -> 217088/SM)

constexpr float CMP_SCALE   = 16777216.f;     // 2^24
constexpr float CMP_INV     = 1.f / 16777216.f;

// Pre-split W planes: [split][row 0..127][j 0..511] of uint2 (4 bf16 each)
__device__ uint2 gW[3][128][512];

__device__ __forceinline__ unsigned cvt2(float hi, float lo) {
    unsigned r; asm("cvt.rn.bf16x2.f32 %0, %1, %2;" : "=r"(r) : "f"(hi), "f"(lo)); return r;
}
__device__ __forceinline__ float blo(unsigned p) { return __uint_as_float(p << 16); }
__device__ __forceinline__ float bhi(unsigned p) { return __uint_as_float(p & 0xffff0000u); }

__device__ __forceinline__ void ldsm4(unsigned* r, uint32_t a) {
    asm volatile("ldmatrix.sync.aligned.m8n8.x4.shared.b16 {%0,%1,%2,%3}, [%4];"
                 : "=r"(r[0]), "=r"(r[1]), "=r"(r[2]), "=r"(r[3]) : "r"(a));
}
__device__ __forceinline__ void mma16816(float* d, const unsigned* a, const unsigned* b) {
    asm volatile("mma.sync.aligned.m16n8k16.row.col.f32.bf16.bf16.f32 "
                 "{%0,%1,%2,%3}, {%4,%5,%6,%7}, {%8,%9}, {%0,%1,%2,%3};"
                 : "+f"(d[0]), "+f"(d[1]), "+f"(d[2]), "+f"(d[3])
                 : "r"(a[0]), "r"(a[1]), "r"(a[2]), "r"(a[3]), "r"(b[0]), "r"(b[1]));
}
__device__ __forceinline__ void cp16(uint32_t dst, const void* src) {
    asm volatile("cp.async.cg.shared.global [%0], [%1], 16;" :: "r"(dst), "l"(src));
}
__device__ __forceinline__ void cp_commit() { asm volatile("cp.async.commit_group;"); }
template <int N>
__device__ __forceinline__ void cp_wait() {
    asm volatile("cp.async.wait_group %0;" :: "n"(N));
}

// exact 3-way split of 4 consecutive fp32 into bf16x2 pairs (h+m+l == x)
__device__ __forceinline__ void split4(float4 v, uint2& h, uint2& m, uint2& l) {
    unsigned h0 = cvt2(v.y, v.x), h1 = cvt2(v.w, v.z);
    float r0 = v.x - blo(h0), r1 = v.y - bhi(h0);
    float r2 = v.z - blo(h1), r3 = v.w - bhi(h1);
    unsigned m0 = cvt2(r1, r0), m1 = cvt2(r3, r2);
    float s0 = r0 - blo(m0), s1 = r1 - bhi(m0);
    float s2 = r2 - blo(m1), s3 = r3 - bhi(m1);
    h = make_uint2(h0, h1);
    m = make_uint2(m0, m1);
    l = make_uint2(cvt2(s1, s0), cvt2(s3, s2));
}

// ---- pre-pass: split W (Wr rows 0-63, Wn rows 64-127) into gW planes ----
__global__ __launch_bounds__(512)
void wconv_kernel(const float* __restrict__ Wr, const float* __restrict__ Wn)
{
    int f = blockIdx.x * 512 + threadIdx.x;
    if (f >= 128 * 512) return;
    int row = f >> 9, j = f & 511;
    const float* src = (row < 64) ? (Wr + (size_t)row * DDIM)
                                  : (Wn + (size_t)(row - 64) * DDIM);
    float4 v = *reinterpret_cast<const float4*>(src + j * 4);
    uint2 h, m, l; split4(v, h, m, l);
    gW[0][row][j] = h;
    gW[1][row][j] = m;
    gW[2][row][j] = l;
}

__global__ __launch_bounds__(NTHR, 2)
void router_kernel(const float* __restrict__ x,
                   const float* __restrict__ bias,
                   const float* __restrict__ nu,
                   float* __restrict__ out_probs,
                   float* __restrict__ out_idx,
                   float* __restrict__ out_bias)
{
    extern __shared__ char sm[];
    const uint32_t smb = (uint32_t)__cvta_generic_to_shared(sm);
    __half* cmpH = reinterpret_cast<__half*>(sm + CMP_OFF);   // [32][NTHR], scaled 2^24

    const int tid  = threadIdx.x;
    const int lane = tid & 31;
    const int wid  = tid >> 5;
    const int token0 = blockIdx.x * TILE_T;

    float acc[2][4][4], mst[2][4][4];
#pragma unroll
    for (int mi = 0; mi < 2; mi++)
#pragma unroll
        for (int ni = 0; ni < 4; ni++)
#pragma unroll
            for (int r = 0; r < 4; r++) { acc[mi][ni][r] = 0.f; mst[mi][ni][r] = 0.f; }
#pragma unroll
    for (int j = 0; j < 32; j++) cmpH[j * NTHR + tid] = __float2half(0.f);

    float4 xv[2];
    auto ldg = [&](int c) {
        const int k0 = c * KC;
#pragma unroll
        for (int r = 0; r < 2; r++) {
            int idx = tid + r * NTHR;
            int row = idx >> 3, kq = idx & 7;
            xv[r] = *reinterpret_cast<const float4*>(
                &x[(size_t)(token0 + row) * DDIM + k0 + kq * 4]);
        }
    };

    auto stsx = [&](int s) {
        char* stage = sm + s * STAGE_B;
#pragma unroll
        for (int r = 0; r < 2; r++) {
            int idx = tid + r * NTHR;
            int row = idx >> 3, kq = idx & 7;
            int off = row * ROWB + kq * 8;
            uint2 h, m, l; split4(xv[r], h, m, l);
            *reinterpret_cast<uint2*>(stage + A_H + off) = h;
            *reinterpret_cast<uint2*>(stage + A_M + off) = m;
            *reinterpret_cast<uint2*>(stage + A_L + off) = l;
        }
    };

    // W tile: 3 planes x 128 rows x 4 x16B = 1536 cp.async -> 6/thread
    auto cpW = [&](int c, int s) {
        const int j0 = c * 8;
        uint32_t base = smb + (uint32_t)(s * STAGE_B + B_H);
#pragma unroll
        for (int r = 0; r < 6; r++) {
            int idx = tid + r * NTHR;          // 0..1535
            int sp = idx >> 9, rem = idx & 511;
            int row = rem >> 2, q = rem & 3;
            cp16(base + (uint32_t)(sp * (128 * ROWB) + row * ROWB + q * 16),
                 &gW[sp][row][j0 + q * 2]);
        }
        cp_commit();
    };

    const int m0 = (wid & 1) * 32;
    const int n0 = (wid >> 1) * 32;
    const int arow = lane & 15, aoff = (lane >> 4) * 16;
    const int q = lane >> 3;
    const int brow = ((q >> 1) * 8) + (lane & 7), boff = (q & 1) * 16;

    auto compute = [&](int st) {
        const uint32_t sb = smb + (uint32_t)(st * STAGE_B);
#pragma unroll
        for (int s = 0; s < 2; s++) {
            unsigned bh[2][4], bm[2][4], bl[2][4];
#pragma unroll
            for (int nb = 0; nb < 2; nb++) {
                uint32_t b = sb + B_H + (n0 + 16 * nb + brow) * ROWB + boff + s * 32;
                ldsm4(bh[nb], b);
                ldsm4(bm[nb], b + (B_M - B_H));
                ldsm4(bl[nb], b + (B_L - B_H));
            }
#pragma unroll
            for (int mi = 0; mi < 2; mi++) {
                unsigned ah[4], am[4], al[4];
                uint32_t a = sb + A_H + (m0 + 16 * mi + arow) * ROWB + aoff + s * 32;
                ldsm4(ah, a);
                ldsm4(am, a + (A_M - A_H));
                ldsm4(al, a + (A_L - A_H));
                // term-major: consecutive MMAs hit different accumulators
#pragma unroll
                for (int ni = 0; ni < 4; ni++)
                    mma16816(acc[mi][ni], ah, &bh[ni >> 1][(ni & 1) * 2]);  // hh
#pragma unroll
                for (int ni = 0; ni < 4; ni++)
                    mma16816(acc[mi][ni], ah, &bm[ni >> 1][(ni & 1) * 2]);  // hm
#pragma unroll
                for (int ni = 0; ni < 4; ni++)
                    mma16816(acc[mi][ni], am, &bh[ni >> 1][(ni & 1) * 2]);  // mh
#pragma unroll
                for (int ni = 0; ni < 4; ni++)
                    mma16816(acc[mi][ni], ah, &bl[ni >> 1][(ni & 1) * 2]);  // hl
#pragma unroll
                for (int ni = 0; ni < 4; ni++)
                    mma16816(acc[mi][ni], am, &bm[ni >> 1][(ni & 1) * 2]);  // mm
#pragma unroll
                for (int ni = 0; ni < 4; ni++)
                    mma16816(acc[mi][ni], al, &bh[ni >> 1][(ni & 1) * 2]);  // lh
            }
        }
    };

    auto drain = [&]() {
#pragma unroll
        for (int mi = 0; mi < 2; mi++)
#pragma unroll
            for (int ni = 0; ni < 4; ni++)
#pragma unroll
                for (int r = 0; r < 4; r++) {
                    int j = ((mi * 4 + ni) * 4 + r);
                    float c0 = __half2float(cmpH[j * NTHR + tid]) * CMP_INV;
                    float y = acc[mi][ni][r] - c0;
                    float t = mst[mi][ni][r] + y;
                    cmpH[j * NTHR + tid] =
                        __float2half(((t - mst[mi][ni][r]) - y) * CMP_SCALE);
                    mst[mi][ni][r] = t;
                    acc[mi][ni][r] = 0.f;
                }
    };

    // ---- prologue ----
    ldg(0);
    cpW(0, 0);
    stsx(0);
    ldg(1);
    cp_wait<0>();
    __syncthreads();

    // ---- main loop ----
    for (int c = 0; c < NCHUNK; c++) {
        if (c + 1 < NCHUNK) { stsx((c + 1) & 1); cpW(c + 1, (c + 1) & 1); }
        if (c + 2 < NCHUNK) ldg(c + 2);
        compute(c & 1);
        if ((c & 3) == 3) drain();
        cp_wait<0>();
        __syncthreads();
    }

    // ---- store masters to zs [64][130] ----
    constexpr int DSTR = 130;
    float* zs = reinterpret_cast<float*>(sm);
    const int dr = lane >> 2, dc = (lane & 3) * 2;
#pragma unroll
    for (int mi = 0; mi < 2; mi++)
#pragma unroll
        for (int ni = 0; ni < 4; ni++) {
            int row = m0 + 16 * mi + dr, col = n0 + 8 * ni + dc;
            *reinterpret_cast<float2*>(&zs[row * DSTR + col]) =
                make_float2(mst[mi][ni][0], mst[mi][ni][1]);
            *reinterpret_cast<float2*>(&zs[(row + 8) * DSTR + col]) =
                make_float2(mst[mi][ni][2], mst[mi][ni][3]);
        }
    __syncthreads();

    // ---- epilogue: z = u*softplus(noisy) + logit + bias; top-8 + softmax ----
    for (int r = 0; r < 8; r++) {
        int tl = wid * 8 + r;
        size_t t = (size_t)token0 + tl;
        float logit0 = zs[tl * DSTR + lane];
        float logit1 = zs[tl * DSTR + lane + 32];
        float noisy0 = zs[tl * DSTR + 64 + lane];
        float noisy1 = zs[tl * DSTR + 96 + lane];
        float u0 = nu[t * E + lane];
        float u1 = nu[t * E + lane + 32];
        float sp0 = fmaxf(noisy0, 0.f) + log1pf(expf(-fabsf(noisy0)));
        float sp1 = fmaxf(noisy1, 0.f) + log1pf(expf(-fabsf(noisy1)));
        float z0 = fmaf(u0, sp0, logit0 + bias[lane]);
        float z1 = fmaf(u1, sp1, logit1 + bias[lane + 32]);

        float v0 = z0, v1 = z1;
        int sel0 = 0, sel1 = 0;
        float m0s = 0.f, denom = 0.f;
        int myidx = 0;
#pragma unroll
        for (int k = 0; k < KSEL; k++) {
            float bv; int bi;
            if (v0 >= v1) { bv = v0; bi = lane; }
            else          { bv = v1; bi = lane + 32; }
#pragma unroll
            for (int off = 16; off > 0; off >>= 1) {
                float ov = __shfl_xor_sync(0xffffffffu, bv, off);
                int   oi = __shfl_xor_sync(0xffffffffu, bi, off);
                if (ov > bv || (ov == bv && oi < bi)) { bv = ov; bi = oi; }
            }
            if (k == 0) m0s = bv;
            denom += expf(bv - m0s);
            if (lane == k) myidx = bi;
            if (bi == lane)           { v0 = -1e30f; sel0 = 1; }
            else if (bi == lane + 32) { v1 = -1e30f; sel1 = 1; }
        }
        float inv = 1.f / denom;
        out_probs[t * E + lane]      = sel0 ? expf(z0 - m0s) * inv : 0.f;
        out_probs[t * E + lane + 32] = sel1 ? expf(z1 - m0s) * inv : 0.f;
        if (lane < KSEL) out_idx[t * KSEL + lane] = (float)myidx;
    }

    // ---- bias update: sign(avg_load - total_selected) == -1 always ----
    if (blockIdx.x == 0 && tid < E) out_bias[tid] = bias[tid] - 0.001f;
}

} // namespace

extern "C" void kernel_launch(void* const* d_in, const int* in_sizes, int n_in,
                              void* d_out, int out_size)
{
    (void)in_sizes; (void)n_in; (void)out_size;
    const float* x    = (const float*)d_in[0];
    const float* Wr   = (const float*)d_in[1];
    const float* Wn   = (const float*)d_in[2];
    const float* bias = (const float*)d_in[3];
    const float* nu   = (const float*)d_in[4];

    float* out   = (float*)d_out;
    float* probs = out;
    float* idx   = out + (size_t)T_TOK * E;
    float* nb    = idx + (size_t)T_TOK * KSEL;

    wconv_kernel<<<128, 512>>>(Wr, Wn);

    cudaFuncSetAttribute(router_kernel, cudaFuncAttributeMaxDynamicSharedMemorySize,
                         SMEM_BYTES);
    router_kernel<<<T_TOK / TILE_T, NTHR, SMEM_BYTES>>>(x, bias, nu,
                                                        probs, idx, nb);
}

// round 14
// speedup vs baseline: 1.0326x; 1.0326x over previous
#include <cuda_runtime.h>
#include <cuda_fp16.h>
#include <math.h>
#include <stdint.h>

// NoisyTopKRouter: B=4, S=4096, D=2048, E=64, K=8
// Exact 3-way bf16 split mma.sync + Kahan (mst fp32 + cmp fp16 in smem);
// B-fragment double-buffering to overlap ldsm bursts with MMA bursts.
// out: probs [T*E] f32, topk_idx [T*K] f32, new_bias [E] f32

namespace {

constexpr int T_TOK  = 16384;
constexpr int DDIM   = 2048;
constexpr int E      = 64;
constexpr int KSEL   = 8;
constexpr int TILE_T = 128;
constexpr int KC     = 32;               // fp32 k per chunk
constexpr int NCHUNK = DDIM / KC;        // 64
constexpr int NTHR   = 512;
constexpr int ROWB   = 80;               // smem row stride bytes (16B-aligned)
constexpr int A_H = 0;
constexpr int A_M = A_H + TILE_T * ROWB;      // 10240
constexpr int A_L = A_M + TILE_T * ROWB;      // 20480
constexpr int B_H = A_L + TILE_T * ROWB;      // 30720
constexpr int B_M = B_H + 128 * ROWB;         // 40960
constexpr int B_L = B_M + 128 * ROWB;         // 51200
constexpr int STAGE_B = B_L + 128 * ROWB;     // 61440
constexpr int MST_OFF = 2 * STAGE_B;          // 122880
constexpr int CMP_OFF = MST_OFF + 32 * NTHR * 4;   // 188416
constexpr int SMEM_BYTES = CMP_OFF + 32 * NTHR * 2; // 221184

constexpr float CMP_SCALE = 16777216.f;       // 2^24
constexpr float CMP_INV   = 1.f / 16777216.f;

// Pre-split W planes: [split][row 0..127][j 0..511] of uint2 (4 bf16 each)
__device__ uint2 gW[3][128][512];

__device__ __forceinline__ unsigned cvt2(float hi, float lo) {
    unsigned r; asm("cvt.rn.bf16x2.f32 %0, %1, %2;" : "=r"(r) : "f"(hi), "f"(lo)); return r;
}
__device__ __forceinline__ float blo(unsigned p) { return __uint_as_float(p << 16); }
__device__ __forceinline__ float bhi(unsigned p) { return __uint_as_float(p & 0xffff0000u); }

__device__ __forceinline__ void ldsm4(unsigned* r, uint32_t a) {
    asm volatile("ldmatrix.sync.aligned.m8n8.x4.shared.b16 {%0,%1,%2,%3}, [%4];"
                 : "=r"(r[0]), "=r"(r[1]), "=r"(r[2]), "=r"(r[3]) : "r"(a));
}
__device__ __forceinline__ void mma16816(float* d, const unsigned* a, const unsigned* b) {
    asm volatile("mma.sync.aligned.m16n8k16.row.col.f32.bf16.bf16.f32 "
                 "{%0,%1,%2,%3}, {%4,%5,%6,%7}, {%8,%9}, {%0,%1,%2,%3};"
                 : "+f"(d[0]), "+f"(d[1]), "+f"(d[2]), "+f"(d[3])
                 : "r"(a[0]), "r"(a[1]), "r"(a[2]), "r"(a[3]), "r"(b[0]), "r"(b[1]));
}
__device__ __forceinline__ void cp16(uint32_t dst, const void* src) {
    asm volatile("cp.async.cg.shared.global [%0], [%1], 16;" :: "r"(dst), "l"(src));
}
__device__ __forceinline__ void cp_commit() { asm volatile("cp.async.commit_group;"); }
template <int N>
__device__ __forceinline__ void cp_wait() {
    asm volatile("cp.async.wait_group %0;" :: "n"(N));
}

// exact 3-way split of 4 consecutive fp32 into bf16x2 pairs (h+m+l == x)
__device__ __forceinline__ void split4(float4 v, uint2& h, uint2& m, uint2& l) {
    unsigned h0 = cvt2(v.y, v.x), h1 = cvt2(v.w, v.z);
    float r0 = v.x - blo(h0), r1 = v.y - bhi(h0);
    float r2 = v.z - blo(h1), r3 = v.w - bhi(h1);
    unsigned m0 = cvt2(r1, r0), m1 = cvt2(r3, r2);
    float s0 = r0 - blo(m0), s1 = r1 - bhi(m0);
    float s2 = r2 - blo(m1), s3 = r3 - bhi(m1);
    h = make_uint2(h0, h1);
    m = make_uint2(m0, m1);
    l = make_uint2(cvt2(s1, s0), cvt2(s3, s2));
}

// ---- pre-pass: split W (Wr rows 0-63, Wn rows 64-127) into gW planes ----
__global__ __launch_bounds__(512)
void wconv_kernel(const float* __restrict__ Wr, const float* __restrict__ Wn)
{
    int f = blockIdx.x * 512 + threadIdx.x;
    if (f >= 128 * 512) return;
    int row = f >> 9, j = f & 511;
    const float* src = (row < 64) ? (Wr + (size_t)row * DDIM)
                                  : (Wn + (size_t)(row - 64) * DDIM);
    float4 v = *reinterpret_cast<const float4*>(src + j * 4);
    uint2 h, m, l; split4(v, h, m, l);
    gW[0][row][j] = h;
    gW[1][row][j] = m;
    gW[2][row][j] = l;
}

__global__ __launch_bounds__(NTHR, 1)
void router_kernel(const float* __restrict__ x,
                   const float* __restrict__ bias,
                   const float* __restrict__ nu,
                   float* __restrict__ out_probs,
                   float* __restrict__ out_idx,
                   float* __restrict__ out_bias)
{
    extern __shared__ char sm[];
    const uint32_t smb = (uint32_t)__cvta_generic_to_shared(sm);
    float*  mstS = reinterpret_cast<float*>(sm + MST_OFF);    // [32][NTHR]
    __half* cmpH = reinterpret_cast<__half*>(sm + CMP_OFF);   // [32][NTHR], scaled 2^24

    const int tid  = threadIdx.x;
    const int lane = tid & 31;
    const int wid  = tid >> 5;
    const int token0 = blockIdx.x * TILE_T;

    float acc[2][4][4];
#pragma unroll
    for (int mi = 0; mi < 2; mi++)
#pragma unroll
        for (int ni = 0; ni < 4; ni++)
#pragma unroll
            for (int r = 0; r < 4; r++) acc[mi][ni][r] = 0.f;
#pragma unroll
    for (int j = 0; j < 32; j++) {
        mstS[j * NTHR + tid] = 0.f;
        cmpH[j * NTHR + tid] = __float2half(0.f);
    }

    float4 xv[2];
    auto ldg = [&](int c) {
        const int k0 = c * KC;
#pragma unroll
        for (int r = 0; r < 2; r++) {
            int idx = tid + r * NTHR;
            int row = idx >> 3, kq = idx & 7;
            xv[r] = *reinterpret_cast<const float4*>(
                &x[(size_t)(token0 + row) * DDIM + k0 + kq * 4]);
        }
    };

    auto stsx = [&](int s) {
        char* stage = sm + s * STAGE_B;
#pragma unroll
        for (int r = 0; r < 2; r++) {
            int idx = tid + r * NTHR;
            int row = idx >> 3, kq = idx & 7;
            int off = row * ROWB + kq * 8;
            uint2 h, m, l; split4(xv[r], h, m, l);
            *reinterpret_cast<uint2*>(stage + A_H + off) = h;
            *reinterpret_cast<uint2*>(stage + A_M + off) = m;
            *reinterpret_cast<uint2*>(stage + A_L + off) = l;
        }
    };

    auto cpW = [&](int c, int s) {
        const int j0 = c * 8;
        uint32_t base = smb + (uint32_t)(s * STAGE_B + B_H);
#pragma unroll
        for (int r = 0; r < 3; r++) {
            int idx = tid + r * NTHR;          // 0..1535
            int sp = idx >> 9, rem = idx & 511;
            int row = rem >> 2, q = rem & 3;
            cp16(base + (uint32_t)(sp * (128 * ROWB) + row * ROWB + q * 16),
                 &gW[sp][row][j0 + q * 2]);
        }
        cp_commit();
    };

    const int m0 = (wid & 3) * 32;
    const int n0 = (wid >> 2) * 32;
    const int arow = lane & 15, aoff = (lane >> 4) * 16;
    const int q = lane >> 3;
    const int brow = ((q >> 1) * 8) + (lane & 7), boff = (q & 1) * 16;

    // B fragments double-buffered across the two k16 sub-steps
    auto ldB = [&](uint32_t sb, int s, unsigned bf[3][2][4]) {
#pragma unroll
        for (int nb = 0; nb < 2; nb++) {
            uint32_t b = sb + B_H + (n0 + 16 * nb + brow) * ROWB + boff + s * 32;
            ldsm4(bf[0][nb], b);
            ldsm4(bf[1][nb], b + (B_M - B_H));
            ldsm4(bf[2][nb], b + (B_L - B_H));
        }
    };

    auto compute = [&](int st) {
        const uint32_t sb = smb + (uint32_t)(st * STAGE_B);
        unsigned bf[2][3][2][4];                 // [buf][plane][nb][reg]
        ldB(sb, 0, bf[0]);
        ldB(sb, 1, bf[1]);                       // prefetch: hides under s=0 MMAs
#pragma unroll
        for (int s = 0; s < 2; s++) {
            unsigned (*bp)[2][4] = bf[s];
#pragma unroll
            for (int mi = 0; mi < 2; mi++) {
                unsigned ah[4], am[4], al[4];
                uint32_t a = sb + A_H + (m0 + 16 * mi + arow) * ROWB + aoff + s * 32;
                ldsm4(ah, a);
                ldsm4(am, a + (A_M - A_H));
                ldsm4(al, a + (A_L - A_H));
                // per-accumulator term order preserved: hh, hm, mh, hl, mm, lh
#pragma unroll
                for (int ni = 0; ni < 4; ni++)
                    mma16816(acc[mi][ni], ah, &bp[0][ni >> 1][(ni & 1) * 2]);  // hh
#pragma unroll
                for (int ni = 0; ni < 4; ni++)
                    mma16816(acc[mi][ni], ah, &bp[1][ni >> 1][(ni & 1) * 2]);  // hm
#pragma unroll
                for (int ni = 0; ni < 4; ni++)
                    mma16816(acc[mi][ni], am, &bp[0][ni >> 1][(ni & 1) * 2]);  // mh
#pragma unroll
                for (int ni = 0; ni < 4; ni++)
                    mma16816(acc[mi][ni], ah, &bp[2][ni >> 1][(ni & 1) * 2]);  // hl
#pragma unroll
                for (int ni = 0; ni < 4; ni++)
                    mma16816(acc[mi][ni], am, &bp[1][ni >> 1][(ni & 1) * 2]);  // mm
#pragma unroll
                for (int ni = 0; ni < 4; ni++)
                    mma16816(acc[mi][ni], al, &bp[0][ni >> 1][(ni & 1) * 2]);  // lh
            }
        }
    };

    auto drain = [&]() {
#pragma unroll
        for (int mi = 0; mi < 2; mi++)
#pragma unroll
            for (int ni = 0; ni < 4; ni++)
#pragma unroll
                for (int r = 0; r < 4; r++) {
                    int j = ((mi * 4 + ni) * 4 + r);
                    float ms = mstS[j * NTHR + tid];
                    float c0 = __half2float(cmpH[j * NTHR + tid]) * CMP_INV;
                    float y = acc[mi][ni][r] - c0;
                    float t = ms + y;
                    cmpH[j * NTHR + tid] = __float2half(((t - ms) - y) * CMP_SCALE);
                    mstS[j * NTHR + tid] = t;
                    acc[mi][ni][r] = 0.f;
                }
    };

    // ---- prologue ----
    ldg(0);
    cpW(0, 0);
    stsx(0);
    ldg(1);
    cp_wait<0>();
    __syncthreads();

    // ---- main loop ----
    for (int c = 0; c < NCHUNK; c++) {
        if (c + 1 < NCHUNK) { stsx((c + 1) & 1); cpW(c + 1, (c + 1) & 1); }
        if (c + 2 < NCHUNK) ldg(c + 2);
        compute(c & 1);
        if ((c & 3) == 3) drain();
        cp_wait<0>();
        __syncthreads();
    }

    // ---- store masters to zs [128][130] (stage area; mst/cmp live above it) ----
    constexpr int DSTR = 130;
    float* zs = reinterpret_cast<float*>(sm);
    const int dr = lane >> 2, dc = (lane & 3) * 2;
#pragma unroll
    for (int mi = 0; mi < 2; mi++)
#pragma unroll
        for (int ni = 0; ni < 4; ni++) {
#pragma unroll
            for (int r = 0; r < 4; r++) {
                int j = ((mi * 4 + ni) * 4 + r);
                int row = m0 + 16 * mi + dr + (r >> 1) * 8;
                int col = n0 + 8 * ni + dc + (r & 1);
                zs[row * DSTR + col] = mstS[j * NTHR + tid];
            }
        }
    __syncthreads();

    // ---- epilogue: z = u*softplus(noisy) + logit + bias; top-8 + softmax ----
    for (int r = 0; r < 8; r++) {
        int tl = wid * 8 + r;
        size_t t = (size_t)token0 + tl;
        float logit0 = zs[tl * DSTR + lane];
        float logit1 = zs[tl * DSTR + lane + 32];
        float noisy0 = zs[tl * DSTR + 64 + lane];
        float noisy1 = zs[tl * DSTR + 96 + lane];
        float u0 = nu[t * E + lane];
        float u1 = nu[t * E + lane + 32];
        float sp0 = fmaxf(noisy0, 0.f) + log1pf(expf(-fabsf(noisy0)));
        float sp1 = fmaxf(noisy1, 0.f) + log1pf(expf(-fabsf(noisy1)));
        float z0 = fmaf(u0, sp0, logit0 + bias[lane]);
        float z1 = fmaf(u1, sp1, logit1 + bias[lane + 32]);

        float v0 = z0, v1 = z1;
        int sel0 = 0, sel1 = 0;
        float m0s = 0.f, denom = 0.f;
        int myidx = 0;
#pragma unroll
        for (int k = 0; k < KSEL; k++) {
            float bv; int bi;
            if (v0 >= v1) { bv = v0; bi = lane; }
            else          { bv = v1; bi = lane + 32; }
#pragma unroll
            for (int off = 16; off > 0; off >>= 1) {
                float ov = __shfl_xor_sync(0xffffffffu, bv, off);
                int   oi = __shfl_xor_sync(0xffffffffu, bi, off);
                if (ov > bv || (ov == bv && oi < bi)) { bv = ov; bi = oi; }
            }
            if (k == 0) m0s = bv;
            denom += expf(bv - m0s);
            if (lane == k) myidx = bi;
            if (bi == lane)           { v0 = -1e30f; sel0 = 1; }
            else if (bi == lane + 32) { v1 = -1e30f; sel1 = 1; }
        }
        float inv = 1.f / denom;
        out_probs[t * E + lane]      = sel0 ? expf(z0 - m0s) * inv : 0.f;
        out_probs[t * E + lane + 32] = sel1 ? expf(z1 - m0s) * inv : 0.f;
        if (lane < KSEL) out_idx[t * KSEL + lane] = (float)myidx;
    }

    // ---- bias update: sign(avg_load - total_selected) == -1 always ----
    if (blockIdx.x == 0 && tid < E) out_bias[tid] = bias[tid] - 0.001f;
}

} // namespace

extern "C" void kernel_launch(void* const* d_in, const int* in_sizes, int n_in,
                              void* d_out, int out_size)
{
    (void)in_sizes; (void)n_in; (void)out_size;
    const float* x    = (const float*)d_in[0];
    const float* Wr   = (const float*)d_in[1];
    const float* Wn   = (const float*)d_in[2];
    const float* bias = (const float*)d_in[3];
    const float* nu   = (const float*)d_in[4];

    float* out   = (float*)d_out;
    float* probs = out;
    float* idx   = out + (size_t)T_TOK * E;
    float* nb    = idx + (size_t)T_TOK * KSEL;

    wconv_kernel<<<128, 512>>>(Wr, Wn);

    cudaFuncSetAttribute(router_kernel, cudaFuncAttributeMaxDynamicSharedMemorySize,
                         SMEM_BYTES);
    router_kernel<<<T_TOK / TILE_T, NTHR, SMEM_BYTES>>>(x, bias, nu,
                                                        probs, idx, nb);
}

// round 15
// speedup vs baseline: 1.6836x; 1.6305x over previous
#include <cuda_runtime.h>
#include <cuda_fp16.h>
#include <math.h>
#include <stdint.h>

// NoisyTopKRouter: B=4, S=4096, D=2048, E=64, K=8
// fp16 2-split (h+l, W pre-scaled 2^10), 3-term mma.sync m16n8k16 f16, Kahan.
// out: probs [T*E] f32, topk_idx [T*K] f32, new_bias [E] f32

namespace {

constexpr int T_TOK  = 16384;
constexpr int DDIM   = 2048;
constexpr int E      = 64;
constexpr int KSEL   = 8;
constexpr int TILE_T = 128;
constexpr int KC     = 32;               // fp32 k per chunk
constexpr int NCHUNK = DDIM / KC;        // 64
constexpr int NTHR   = 512;
constexpr int ROWB   = 80;               // smem row stride bytes (16B-aligned)
constexpr int A_H = 0;
constexpr int A_L = A_H + TILE_T * ROWB;      // 10240
constexpr int B_H = A_L + TILE_T * ROWB;      // 20480
constexpr int B_L = B_H + 128 * ROWB;         // 30720
constexpr int STAGE_B = B_L + 128 * ROWB;     // 40960
constexpr int CMP_OFF = 2 * STAGE_B;          // 81920
constexpr int SMEM_BYTES = CMP_OFF + 32 * NTHR * 4;   // 147456

constexpr float WSCALE   = 1024.f;            // 2^10 (keeps w_l out of subnormals)
constexpr float WSCALE_I = 1.f / 1024.f;

// Pre-split scaled-W planes: [plane h/l][row 0..127][j 0..511] of uint2 (4 fp16)
__device__ uint2 gW[2][128][512];

__device__ __forceinline__ unsigned h2pack(float hi, float lo) {
    unsigned r; asm("cvt.rn.f16x2.f32 %0, %1, %2;" : "=r"(r) : "f"(hi), "f"(lo)); return r;
}
__device__ __forceinline__ float h2lo(unsigned p) {
    float f; asm("cvt.f32.f16 %0, %1;" : "=f"(f) : "h"((unsigned short)(p & 0xffff)));
    return f;
}
__device__ __forceinline__ float h2hi(unsigned p) {
    float f; asm("cvt.f32.f16 %0, %1;" : "=f"(f) : "h"((unsigned short)(p >> 16)));
    return f;
}

__device__ __forceinline__ void ldsm4(unsigned* r, uint32_t a) {
    asm volatile("ldmatrix.sync.aligned.m8n8.x4.shared.b16 {%0,%1,%2,%3}, [%4];"
                 : "=r"(r[0]), "=r"(r[1]), "=r"(r[2]), "=r"(r[3]) : "r"(a));
}
__device__ __forceinline__ void mma16816(float* d, const unsigned* a, const unsigned* b) {
    asm volatile("mma.sync.aligned.m16n8k16.row.col.f32.f16.f16.f32 "
                 "{%0,%1,%2,%3}, {%4,%5,%6,%7}, {%8,%9}, {%0,%1,%2,%3};"
                 : "+f"(d[0]), "+f"(d[1]), "+f"(d[2]), "+f"(d[3])
                 : "r"(a[0]), "r"(a[1]), "r"(a[2]), "r"(a[3]), "r"(b[0]), "r"(b[1]));
}
__device__ __forceinline__ void cp16(uint32_t dst, const void* src) {
    asm volatile("cp.async.cg.shared.global [%0], [%1], 16;" :: "r"(dst), "l"(src));
}
__device__ __forceinline__ void cp_commit() { asm volatile("cp.async.commit_group;"); }
template <int N>
__device__ __forceinline__ void cp_wait() {
    asm volatile("cp.async.wait_group %0;" :: "n"(N));
}

// 2-way fp16 split of 4 consecutive fp32 (h + l ~= x, residual ~2^-22)
__device__ __forceinline__ void split4h(float4 v, uint2& h, uint2& l) {
    unsigned h0 = h2pack(v.y, v.x), h1 = h2pack(v.w, v.z);
    float r0 = v.x - h2lo(h0), r1 = v.y - h2hi(h0);
    float r2 = v.z - h2lo(h1), r3 = v.w - h2hi(h1);
    h = make_uint2(h0, h1);
    l = make_uint2(h2pack(r1, r0), h2pack(r3, r2));
}

// ---- pre-pass: scale W by 2^10 and split (Wr rows 0-63, Wn rows 64-127) ----
__global__ __launch_bounds__(512)
void wconv_kernel(const float* __restrict__ Wr, const float* __restrict__ Wn)
{
    int f = blockIdx.x * 512 + threadIdx.x;
    if (f >= 128 * 512) return;
    int row = f >> 9, j = f & 511;
    const float* src = (row < 64) ? (Wr + (size_t)row * DDIM)
                                  : (Wn + (size_t)(row - 64) * DDIM);
    float4 v = *reinterpret_cast<const float4*>(src + j * 4);
    v.x *= WSCALE; v.y *= WSCALE; v.z *= WSCALE; v.w *= WSCALE;
    uint2 h, l; split4h(v, h, l);
    gW[0][row][j] = h;
    gW[1][row][j] = l;
}

__global__ __launch_bounds__(NTHR, 1)
void router_kernel(const float* __restrict__ x,
                   const float* __restrict__ bias,
                   const float* __restrict__ nu,
                   float* __restrict__ out_probs,
                   float* __restrict__ out_idx,
                   float* __restrict__ out_bias)
{
    extern __shared__ char sm[];
    const uint32_t smb = (uint32_t)__cvta_generic_to_shared(sm);
    float* cmpS = reinterpret_cast<float*>(sm + CMP_OFF);   // [32][NTHR]

    const int tid  = threadIdx.x;
    const int lane = tid & 31;
    const int wid  = tid >> 5;
    const int token0 = blockIdx.x * TILE_T;

    float acc[2][4][4], mst[2][4][4];
#pragma unroll
    for (int mi = 0; mi < 2; mi++)
#pragma unroll
        for (int ni = 0; ni < 4; ni++)
#pragma unroll
            for (int r = 0; r < 4; r++) { acc[mi][ni][r] = 0.f; mst[mi][ni][r] = 0.f; }
#pragma unroll
    for (int j = 0; j < 32; j++) cmpS[j * NTHR + tid] = 0.f;

    float4 xv[2];
    auto ldg = [&](int c) {
        const int k0 = c * KC;
#pragma unroll
        for (int r = 0; r < 2; r++) {
            int idx = tid + r * NTHR;
            int row = idx >> 3, kq = idx & 7;
            xv[r] = *reinterpret_cast<const float4*>(
                &x[(size_t)(token0 + row) * DDIM + k0 + kq * 4]);
        }
    };

    auto stsx = [&](int s) {
        char* stage = sm + s * STAGE_B;
#pragma unroll
        for (int r = 0; r < 2; r++) {
            int idx = tid + r * NTHR;
            int row = idx >> 3, kq = idx & 7;
            int off = row * ROWB + kq * 8;
            uint2 h, l; split4h(xv[r], h, l);
            *reinterpret_cast<uint2*>(stage + A_H + off) = h;
            *reinterpret_cast<uint2*>(stage + A_L + off) = l;
        }
    };

    // W tile: 2 planes x 128 rows x 4 x16B = 1024 cp.async -> 2/thread
    auto cpW = [&](int c, int s) {
        const int j0 = c * 8;
        uint32_t base = smb + (uint32_t)(s * STAGE_B + B_H);
#pragma unroll
        for (int r = 0; r < 2; r++) {
            int idx = tid + r * NTHR;          // 0..1023
            int sp = idx >> 9, rem = idx & 511;
            int row = rem >> 2, q = rem & 3;
            cp16(base + (uint32_t)(sp * (128 * ROWB) + row * ROWB + q * 16),
                 &gW[sp][row][j0 + q * 2]);
        }
        cp_commit();
    };

    const int m0 = (wid & 3) * 32;
    const int n0 = (wid >> 2) * 32;
    const int arow = lane & 15, aoff = (lane >> 4) * 16;
    const int q = lane >> 3;
    const int brow = ((q >> 1) * 8) + (lane & 7), boff = (q & 1) * 16;

    auto compute = [&](int st) {
        const uint32_t sb = smb + (uint32_t)(st * STAGE_B);
#pragma unroll
        for (int s = 0; s < 2; s++) {
            unsigned bh[2][4], bl[2][4];
#pragma unroll
            for (int nb = 0; nb < 2; nb++) {
                uint32_t b = sb + B_H + (n0 + 16 * nb + brow) * ROWB + boff + s * 32;
                ldsm4(bh[nb], b);
                ldsm4(bl[nb], b + (B_L - B_H));
            }
#pragma unroll
            for (int mi = 0; mi < 2; mi++) {
                unsigned ah[4], al[4];
                uint32_t a = sb + A_H + (m0 + 16 * mi + arow) * ROWB + aoff + s * 32;
                ldsm4(ah, a);
                ldsm4(al, a + (A_L - A_H));
                // per-accumulator term order: hh, hl, lh
#pragma unroll
                for (int ni = 0; ni < 4; ni++)
                    mma16816(acc[mi][ni], ah, &bh[ni >> 1][(ni & 1) * 2]);  // hh
#pragma unroll
                for (int ni = 0; ni < 4; ni++)
                    mma16816(acc[mi][ni], ah, &bl[ni >> 1][(ni & 1) * 2]);  // hl
#pragma unroll
                for (int ni = 0; ni < 4; ni++)
                    mma16816(acc[mi][ni], al, &bh[ni >> 1][(ni & 1) * 2]);  // lh
            }
        }
    };

    auto drain = [&]() {
#pragma unroll
        for (int mi = 0; mi < 2; mi++)
#pragma unroll
            for (int ni = 0; ni < 4; ni++)
#pragma unroll
                for (int r = 0; r < 4; r++) {
                    int j = ((mi * 4 + ni) * 4 + r);
                    float c0 = cmpS[j * NTHR + tid];
                    float y = acc[mi][ni][r] - c0;
                    float t = mst[mi][ni][r] + y;
                    cmpS[j * NTHR + tid] = (t - mst[mi][ni][r]) - y;
                    mst[mi][ni][r] = t;
                    acc[mi][ni][r] = 0.f;
                }
    };

    // ---- prologue ----
    ldg(0);
    cpW(0, 0);
    stsx(0);
    ldg(1);
    cp_wait<0>();
    __syncthreads();

    // ---- main loop ----
    for (int c = 0; c < NCHUNK; c++) {
        if (c + 1 < NCHUNK) { stsx((c + 1) & 1); cpW(c + 1, (c + 1) & 1); }
        if (c + 2 < NCHUNK) ldg(c + 2);
        compute(c & 1);
        if ((c & 3) == 3) drain();
        cp_wait<0>();
        __syncthreads();
    }

    // ---- store masters to zs [128][130], unscaling by 2^-10 ----
    constexpr int DSTR = 130;
    float* zs = reinterpret_cast<float*>(sm);
    const int dr = lane >> 2, dc = (lane & 3) * 2;
#pragma unroll
    for (int mi = 0; mi < 2; mi++)
#pragma unroll
        for (int ni = 0; ni < 4; ni++) {
            int row = m0 + 16 * mi + dr, col = n0 + 8 * ni + dc;
            *reinterpret_cast<float2*>(&zs[row * DSTR + col]) =
                make_float2(mst[mi][ni][0] * WSCALE_I, mst[mi][ni][1] * WSCALE_I);
            *reinterpret_cast<float2*>(&zs[(row + 8) * DSTR + col]) =
                make_float2(mst[mi][ni][2] * WSCALE_I, mst[mi][ni][3] * WSCALE_I);
        }
    __syncthreads();

    // ---- epilogue: z = u*softplus(noisy) + logit + bias; top-8 + softmax ----
    for (int r = 0; r < 8; r++) {
        int tl = wid * 8 + r;
        size_t t = (size_t)token0 + tl;
        float logit0 = zs[tl * DSTR + lane];
        float logit1 = zs[tl * DSTR + lane + 32];
        float noisy0 = zs[tl * DSTR + 64 + lane];
        float noisy1 = zs[tl * DSTR + 96 + lane];
        float u0 = nu[t * E + lane];
        float u1 = nu[t * E + lane + 32];
        float sp0 = fmaxf(noisy0, 0.f) + log1pf(expf(-fabsf(noisy0)));
        float sp1 = fmaxf(noisy1, 0.f) + log1pf(expf(-fabsf(noisy1)));
        float z0 = fmaf(u0, sp0, logit0 + bias[lane]);
        float z1 = fmaf(u1, sp1, logit1 + bias[lane + 32]);

        float v0 = z0, v1 = z1;
        int sel0 = 0, sel1 = 0;
        float m0s = 0.f, denom = 0.f;
        int myidx = 0;
#pragma unroll
        for (int k = 0; k < KSEL; k++) {
            float bv; int bi;
            if (v0 >= v1) { bv = v0; bi = lane; }
            else          { bv = v1; bi = lane + 32; }
#pragma unroll
            for (int off = 16; off > 0; off >>= 1) {
                float ov = __shfl_xor_sync(0xffffffffu, bv, off);
                int   oi = __shfl_xor_sync(0xffffffffu, bi, off);
                if (ov > bv || (ov == bv && oi < bi)) { bv = ov; bi = oi; }
            }
            if (k == 0) m0s = bv;
            denom += expf(bv - m0s);
            if (lane == k) myidx = bi;
            if (bi == lane)           { v0 = -1e30f; sel0 = 1; }
            else if (bi == lane + 32) { v1 = -1e30f; sel1 = 1; }
        }
        float inv = 1.f / denom;
        out_probs[t * E + lane]      = sel0 ? expf(z0 - m0s) * inv : 0.f;
        out_probs[t * E + lane + 32] = sel1 ? expf(z1 - m0s) * inv : 0.f;
        if (lane < KSEL) out_idx[t * KSEL + lane] = (float)myidx;
    }

    // ---- bias update: sign(avg_load - total_selected) == -1 always ----
    if (blockIdx.x == 0 && tid < E) out_bias[tid] = bias[tid] - 0.001f;
}

} // namespace

extern "C" void kernel_launch(void* const* d_in, const int* in_sizes, int n_in,
                              void* d_out, int out_size)
{
    (void)in_sizes; (void)n_in; (void)out_size;
    const float* x    = (const float*)d_in[0];
    const float* Wr   = (const float*)d_in[1];
    const float* Wn   = (const float*)d_in[2];
    const float* bias = (const float*)d_in[3];
    const float* nu   = (const float*)d_in[4];

    float* out   = (float*)d_out;
    float* probs = out;
    float* idx   = out + (size_t)T_TOK * E;
    float* nb    = idx + (size_t)T_TOK * KSEL;

    wconv_kernel<<<128, 512>>>(Wr, Wn);

    cudaFuncSetAttribute(router_kernel, cudaFuncAttributeMaxDynamicSharedMemorySize,
                         SMEM_BYTES);
    router_kernel<<<T_TOK / TILE_T, NTHR, SMEM_BYTES>>>(x, bias, nu,
                                                        probs, idx, nb);
}